// round 2
// baseline (speedup 1.0000x reference)
#include <cuda_runtime.h>
#include <math.h>

// Problem constants
#define NN   50000
#define EE   800000
#define DD   128
#define HH   4
#define EDD  32
#define KDIM 129          // D+1 input dim
#define QKS  132          // per-(n,h) stride for q/k: [space 0..127, time at 128, pad]
#define EPSF 1e-8f
#define SCALE_INV 0.08838834764831845f   // 1/sqrt(128)
#define CHALF     5.656854249492381f     // sqrt(128)/2

// ---------------- scratch (static device globals; no allocation) -------------
__device__ float g_q[NN * HH * QKS];      // 105.6 MB
__device__ float g_k[NN * HH * QKS];      // 105.6 MB
__device__ float g_tan[NN * HH * DD];     // 102.4 MB
__device__ float g_logits[EE * HH];       // 12.8 MB (reused as exp values)
__device__ float g_m[NN * HH];
__device__ float g_den[NN * HH];
__device__ float g_agg[NN * HH * DD];     // 102.4 MB

// ---------------------------------------------------------------------------
__global__ void k_init() {
    int i = blockIdx.x * blockDim.x + threadIdx.x;
    int stride = gridDim.x * blockDim.x;
    for (int j = i; j < NN * HH * DD; j += stride) g_agg[j] = 0.f;
    for (int j = i; j < NN * HH; j += stride) { g_m[j] = -3.0e38f; g_den[j] = 0.f; }
}

// ---------------- fused q/k/v GEMM + epilogue -------------------------------
// grid: (ceil(N/64), 12) ; blockIdx.y -> which(0=q,1=k,2=v) * head
// block: 256 threads = 16(tx) x 16(ty). Each thread: 4 nodes x 8 outputs.
#define GTM 64
#define GKT 16
__global__ void k_gemm(const float* __restrict__ x,
                       const float* __restrict__ Wq, const float* __restrict__ bq,
                       const float* __restrict__ Wk, const float* __restrict__ bk,
                       const float* __restrict__ Wv, const float* __restrict__ bv) {
    int which = blockIdx.y >> 2;
    int h = blockIdx.y & 3;
    const float* W = (which == 0) ? Wq : ((which == 1) ? Wk : Wv);
    const float* b = (which == 0) ? bq : ((which == 1) ? bk : bv);
    W += h * DD * KDIM;
    b += h * DD;
    int n0 = blockIdx.x * GTM;

    __shared__ float As[GKT][GTM];    // 16x64
    __shared__ float Bs[GKT][DD];     // 16x128
    __shared__ float fac[GTM];

    int t = threadIdx.x;
    int tx = t & 15, ty = t >> 4;

    float acc[4][8];
#pragma unroll
    for (int j = 0; j < 4; j++)
#pragma unroll
        for (int c = 0; c < 8; c++) acc[j][c] = 0.f;

    for (int kk = 0; kk < KDIM; kk += GKT) {
        // load A tile: 64 nodes x 16 k
#pragma unroll
        for (int r = 0; r < 4; r++) {
            int idx = t + r * 256;
            int nn = idx >> 4, k = idx & 15;
            int gi = kk + k, gn = n0 + nn;
            float v = 0.f;
            if (gi < KDIM && gn < NN) v = x[gn * KDIM + gi];
            As[k][nn] = v;
        }
        // load B tile: 128 outputs x 16 k
#pragma unroll
        for (int r = 0; r < 8; r++) {
            int idx = t + r * 256;
            int o = idx >> 4, k = idx & 15;
            int gi = kk + k;
            float v = 0.f;
            if (gi < KDIM) v = W[o * KDIM + gi];
            Bs[k][o] = v;
        }
        __syncthreads();
#pragma unroll
        for (int k = 0; k < GKT; k++) {
            float4 av = ((const float4*)As)[k * 16 + ty];
            float4 b0 = ((const float4*)Bs)[k * 32 + tx];
            float4 b1 = ((const float4*)Bs)[k * 32 + 16 + tx];
            float a[4] = {av.x, av.y, av.z, av.w};
            float bb[8] = {b0.x, b0.y, b0.z, b0.w, b1.x, b1.y, b1.z, b1.w};
#pragma unroll
            for (int j = 0; j < 4; j++)
#pragma unroll
                for (int c = 0; c < 8; c++) acc[j][c] = fmaf(a[j], bb[c], acc[j][c]);
        }
        __syncthreads();
    }

    // add bias (before row-norm, per reference)
#pragma unroll
    for (int c = 0; c < 8; c++) {
        int o = (c < 4) ? (tx * 4 + c) : (64 + tx * 4 + (c - 4));
        float bb = b[o];
#pragma unroll
        for (int j = 0; j < 4; j++) acc[j][c] += bb;
    }

    // per-node sum of squares across the 16 tx threads (reuse As as 64x16)
    float* red = &As[0][0];
#pragma unroll
    for (int j = 0; j < 4; j++) {
        float s = 0.f;
#pragma unroll
        for (int c = 0; c < 8; c++) s = fmaf(acc[j][c], acc[j][c], s);
        red[(ty * 4 + j) * 16 + tx] = s;
    }
    __syncthreads();
    if (t < GTM) {
        float ss = 0.f;
#pragma unroll
        for (int i = 0; i < 16; i++) ss += red[t * 16 + i];
        int gn = n0 + t;
        if (which == 2) {
            float ns = sqrtf(ss);
            fac[t] = asinhf(ns) / fmaxf(ns, EPSF);   // tangent rescale
        } else {
            fac[t] = 1.f;
            if (gn < NN) {
                float* dst = (which == 0) ? g_q : g_k;
                dst[((size_t)gn * HH + h) * QKS + 128] = sqrtf(ss + 1.0f); // time
            }
        }
    }
    __syncthreads();

    // write space components
#pragma unroll
    for (int j = 0; j < 4; j++) {
        int nl = ty * 4 + j;
        int gn = n0 + nl;
        if (gn >= NN) continue;
        float f = fac[nl];
        float4 v0 = make_float4(acc[j][0] * f, acc[j][1] * f, acc[j][2] * f, acc[j][3] * f);
        float4 v1 = make_float4(acc[j][4] * f, acc[j][5] * f, acc[j][6] * f, acc[j][7] * f);
        if (which == 2) {
            float* base = g_tan + ((size_t)gn * HH + h) * DD;
            ((float4*)base)[tx] = v0;
            ((float4*)base)[16 + tx] = v1;
        } else {
            float* base = ((which == 0) ? g_q : g_k) + ((size_t)gn * HH + h) * QKS;
            ((float4*)base)[tx] = v0;
            ((float4*)base)[16 + tx] = v1;
        }
    }
}

// ---------------- edge phase ------------------------------------------------
__device__ __forceinline__ void atomicMaxF(float* addr, float v) {
    if (v >= 0.f) atomicMax((int*)addr, __float_as_int(v));
    else          atomicMin((unsigned int*)addr, __float_as_uint(v));
}

// warp per edge: compute logits (all 4 heads) + atomic segment max
__global__ void k_edge1(const int* __restrict__ ei,
                        const float* __restrict__ ef,
                        const float* __restrict__ We) {
    int w = (blockIdx.x * blockDim.x + threadIdx.x) >> 5;
    int lane = threadIdx.x & 31;
    if (w >= EE) return;
    int s = ei[w];
    int d = ei[EE + w];
    float efl = ef[(size_t)w * EDD + lane];

    const float* qb = g_q + (size_t)d * (HH * QKS);
    const float* kb = g_k + (size_t)s * (HH * QKS);
    float part[HH];
#pragma unroll
    for (int h = 0; h < HH; h++) {
        const float* qh = qb + h * QKS;
        const float* kh = kb + h * QKS;
        float p = 0.f;
#pragma unroll
        for (int i = lane; i < 129; i += 32) {
            float qv = __ldg(qh + i);
            float kv = __ldg(kh + i);
            p = fmaf((i == 128) ? -qv : qv, kv, p);   // Minkowski sign on time
        }
        // fold edge-feature term so one reduction suffices
        p = fmaf(CHALF * efl, __ldg(We + h * EDD + lane), p);
        part[h] = p;
    }
#pragma unroll
    for (int off = 16; off > 0; off >>= 1) {
#pragma unroll
        for (int h = 0; h < HH; h++)
            part[h] += __shfl_xor_sync(0xffffffffu, part[h], off);
    }
    if (lane < HH) {
        float logit = (2.f + 2.f * part[lane]) * SCALE_INV;
        g_logits[(size_t)w * HH + lane] = logit;
        atomicMaxF(&g_m[(size_t)d * HH + lane], logit);
    }
}

// thread per (edge, head): exp + segment sum of denominator
__global__ void k_edge2(const int* __restrict__ ei) {
    int idx = blockIdx.x * blockDim.x + threadIdx.x;
    if (idx >= EE * HH) return;
    int e = idx >> 2, h = idx & 3;
    int d = ei[EE + e];
    float ex = expf(g_logits[idx] - g_m[(size_t)d * HH + h]);
    g_logits[idx] = ex;
    atomicAdd(&g_den[(size_t)d * HH + h], ex);
}

// warp per edge: alpha * tan[src] scattered into agg[dst]
__global__ void k_edge3(const int* __restrict__ ei) {
    int w = (blockIdx.x * blockDim.x + threadIdx.x) >> 5;
    int lane = threadIdx.x & 31;
    if (w >= EE) return;
    int s = ei[w];
    int d = ei[EE + w];
    float a_l = 0.f;
    if (lane < HH) a_l = g_logits[(size_t)w * HH + lane] / g_den[(size_t)d * HH + lane];
    float alpha[HH];
#pragma unroll
    for (int h = 0; h < HH; h++) alpha[h] = __shfl_sync(0xffffffffu, a_l, h);

#pragma unroll
    for (int h = 0; h < HH; h++) {
        float4 t4 = ((const float4*)g_tan)[((size_t)s * HH + h) * 32 + lane];
        float* dp = g_agg + ((size_t)d * HH + h) * DD + lane * 4;
        atomicAdd(dp + 0, alpha[h] * t4.x);
        atomicAdd(dp + 1, alpha[h] * t4.y);
        atomicAdd(dp + 2, alpha[h] * t4.z);
        atomicAdd(dp + 3, alpha[h] * t4.w);
    }
}

// ---------------- output: mean over heads + expmap0 -------------------------
// warp per node
__global__ void k_out(float* __restrict__ out) {
    int w = (blockIdx.x * blockDim.x + threadIdx.x) >> 5;
    int lane = threadIdx.x & 31;
    if (w >= NN) return;
    float4 ms = make_float4(0.f, 0.f, 0.f, 0.f);
#pragma unroll
    for (int h = 0; h < HH; h++) {
        float4 v = ((const float4*)g_agg)[((size_t)w * HH + h) * 32 + lane];
        ms.x += v.x; ms.y += v.y; ms.z += v.z; ms.w += v.w;
    }
    ms.x *= 0.25f; ms.y *= 0.25f; ms.z *= 0.25f; ms.w *= 0.25f;
    float ss = ms.x * ms.x + ms.y * ms.y + ms.z * ms.z + ms.w * ms.w;
#pragma unroll
    for (int off = 16; off > 0; off >>= 1) ss += __shfl_xor_sync(0xffffffffu, ss, off);
    float nrm = sqrtf(ss);
    float f = sinhf(nrm) / fmaxf(nrm, EPSF);
    float* op = out + (size_t)w * KDIM;
    if (lane == 0) op[0] = coshf(nrm);
    float* sp = op + 1 + lane * 4;
    sp[0] = f * ms.x; sp[1] = f * ms.y; sp[2] = f * ms.z; sp[3] = f * ms.w;
}

// ---------------------------------------------------------------------------
extern "C" void kernel_launch(void* const* d_in, const int* in_sizes, int n_in,
                              void* d_out, int out_size) {
    const float* x  = (const float*)d_in[0];
    const int*   ei = (const int*)d_in[1];
    const float* ef = (const float*)d_in[2];
    const float* Wq = (const float*)d_in[3];
    const float* bq = (const float*)d_in[4];
    const float* Wk = (const float*)d_in[5];
    const float* bk = (const float*)d_in[6];
    const float* Wv = (const float*)d_in[7];
    const float* bv = (const float*)d_in[8];
    const float* We = (const float*)d_in[9];
    float* out = (float*)d_out;

    k_init<<<2048, 256>>>();
    k_gemm<<<dim3((NN + GTM - 1) / GTM, 12), 256>>>(x, Wq, bq, Wk, bk, Wv, bv);
    k_edge1<<<(EE * 32) / 256, 256>>>(ei, ef, We);
    k_edge2<<<(EE * HH + 255) / 256, 256>>>(ei);
    k_edge3<<<(EE * 32) / 256, 256>>>(ei);
    k_out<<<(NN * 32 + 255) / 256, 256>>>(out);
}

// round 3
// speedup vs baseline: 1.7017x; 1.7017x over previous
#include <cuda_runtime.h>
#include <math.h>

// Problem constants
#define NN   50000
#define EE   800000
#define DD   128
#define HH   4
#define EDD  32
#define KDIM 129          // D+1 input dim
#define QKS  132          // per-(n,h) stride for q/k: [space 0..127, time at 128, pad]
#define EPSF 1e-8f
#define SCALE_INV 0.08838834764831845f   // 1/sqrt(128)
#define CHALF     5.656854249492381f     // sqrt(128)/2

// ---------------- scratch (static device globals; no allocation) -------------
__device__ float g_q[NN * HH * QKS];      // 105.6 MB
__device__ float g_k[NN * HH * QKS];      // 105.6 MB
__device__ float g_tan[NN * HH * DD];     // 102.4 MB
__device__ float g_logits[EE * HH];       // 12.8 MB (reused as exp values)
__device__ float g_m[NN * HH];
__device__ float g_den[NN * HH];
__device__ float g_agg[NN * HH * DD];     // 102.4 MB

// ---------------------------------------------------------------------------
__global__ void k_init() {
    int i = blockIdx.x * blockDim.x + threadIdx.x;
    int stride = gridDim.x * blockDim.x;
    for (int j = i; j < NN * HH * DD; j += stride) g_agg[j] = 0.f;
    for (int j = i; j < NN * HH; j += stride) { g_m[j] = -3.0e38f; g_den[j] = 0.f; }
}

// ---------------- fused q/k/v GEMM + epilogue -------------------------------
// grid: (ceil(N/128), 12) ; blockIdx.y -> which(0=q,1=k,2=v)*4 + head
// block: 256 threads = 16(tx: n-dim) x 16(ty: m-dim). Each thread: 8 nodes x 8 outputs.
#define BM 128
#define BK 16
__global__ void __launch_bounds__(256, 2)
k_gemm(const float* __restrict__ x,
       const float* __restrict__ Wq, const float* __restrict__ bq,
       const float* __restrict__ Wk, const float* __restrict__ bk,
       const float* __restrict__ Wv, const float* __restrict__ bv) {
    int which = blockIdx.y >> 2;
    int h = blockIdx.y & 3;
    const float* W = (which == 0) ? Wq : ((which == 1) ? Wk : Wv);
    const float* b = (which == 0) ? bq : ((which == 1) ? bk : bv);
    W += h * DD * KDIM;
    b += h * DD;
    int n0 = blockIdx.x * BM;

    __shared__ float As[BK][BM + 4];    // A tile (k-major)
    __shared__ float Bs[BK][DD + 4];    // B tile (k-major)
    __shared__ float red[BM][17];       // row sum-of-squares partials
    __shared__ float fac[BM];

    int t = threadIdx.x;
    int tx = t & 15, ty = t >> 4;

    float acc[8][8];
#pragma unroll
    for (int j = 0; j < 8; j++)
#pragma unroll
        for (int c = 0; c < 8; c++) acc[j][c] = 0.f;

    for (int kk = 0; kk < KDIM; kk += BK) {
        // load A tile: 128 nodes x 16 k  (2048 elems, 8/thread)
#pragma unroll
        for (int r = 0; r < 8; r++) {
            int idx = r * 256 + t;
            int m = idx >> 4, k = idx & 15;
            int gi = kk + k, gn = n0 + m;
            float v = 0.f;
            if (gi < KDIM && gn < NN) v = x[(size_t)gn * KDIM + gi];
            As[k][m] = v;
        }
        // load B tile: 128 outputs x 16 k
#pragma unroll
        for (int r = 0; r < 8; r++) {
            int idx = r * 256 + t;
            int o = idx >> 4, k = idx & 15;
            int gi = kk + k;
            float v = 0.f;
            if (gi < KDIM) v = W[o * KDIM + gi];
            Bs[k][o] = v;
        }
        __syncthreads();
#pragma unroll
        for (int k = 0; k < BK; k++) {
            float4 a0 = *(const float4*)&As[k][ty * 8];
            float4 a1 = *(const float4*)&As[k][ty * 8 + 4];
            float4 b0 = *(const float4*)&Bs[k][tx * 8];
            float4 b1 = *(const float4*)&Bs[k][tx * 8 + 4];
            float a[8] = {a0.x, a0.y, a0.z, a0.w, a1.x, a1.y, a1.z, a1.w};
            float bb[8] = {b0.x, b0.y, b0.z, b0.w, b1.x, b1.y, b1.z, b1.w};
#pragma unroll
            for (int j = 0; j < 8; j++)
#pragma unroll
                for (int c = 0; c < 8; c++) acc[j][c] = fmaf(a[j], bb[c], acc[j][c]);
        }
        __syncthreads();
    }

    // add bias
#pragma unroll
    for (int c = 0; c < 8; c++) {
        float bb = b[tx * 8 + c];
#pragma unroll
        for (int j = 0; j < 8; j++) acc[j][c] += bb;
    }

    // per-node sum of squares across the 16 tx threads
#pragma unroll
    for (int j = 0; j < 8; j++) {
        float s = 0.f;
#pragma unroll
        for (int c = 0; c < 8; c++) s = fmaf(acc[j][c], acc[j][c], s);
        red[ty * 8 + j][tx] = s;
    }
    __syncthreads();
    if (t < BM) {
        float ss = 0.f;
#pragma unroll
        for (int i = 0; i < 16; i++) ss += red[t][i];
        int gn = n0 + t;
        if (which == 2) {
            float ns = sqrtf(ss);
            fac[t] = asinhf(ns) / fmaxf(ns, EPSF);   // tangent rescale
        } else {
            fac[t] = 1.f;
            if (gn < NN) {
                float* dst = (which == 0) ? g_q : g_k;
                dst[((size_t)gn * HH + h) * QKS + 128] = sqrtf(ss + 1.0f); // time
            }
        }
    }
    __syncthreads();

    // write space components (cols tx*8 .. tx*8+7)
#pragma unroll
    for (int j = 0; j < 8; j++) {
        int m = ty * 8 + j;
        int gn = n0 + m;
        if (gn >= NN) continue;
        float f = fac[m];
        float4 v0 = make_float4(acc[j][0] * f, acc[j][1] * f, acc[j][2] * f, acc[j][3] * f);
        float4 v1 = make_float4(acc[j][4] * f, acc[j][5] * f, acc[j][6] * f, acc[j][7] * f);
        float* base;
        if (which == 2) base = g_tan + ((size_t)gn * HH + h) * DD;
        else            base = ((which == 0) ? g_q : g_k) + ((size_t)gn * HH + h) * QKS;
        ((float4*)(base + tx * 8))[0] = v0;
        ((float4*)(base + tx * 8))[1] = v1;
    }
}

// ---------------- edge phase ------------------------------------------------
__device__ __forceinline__ void atomicMaxF(float* addr, float v) {
    if (v >= 0.f) atomicMax((int*)addr, __float_as_int(v));
    else          atomicMin((unsigned int*)addr, __float_as_uint(v));
}

// warp per edge: compute logits (all 4 heads) + atomic segment max
__global__ void k_edge1(const int* __restrict__ ei,
                        const float* __restrict__ ef,
                        const float* __restrict__ We) {
    int w = (blockIdx.x * blockDim.x + threadIdx.x) >> 5;
    int lane = threadIdx.x & 31;
    if (w >= EE) return;
    int s = ei[w];
    int d = ei[EE + w];
    float efl = __ldg(ef + (size_t)w * EDD + lane);

    const float* qb = g_q + (size_t)d * (HH * QKS);
    const float* kb = g_k + (size_t)s * (HH * QKS);
    float part[HH];
#pragma unroll
    for (int h = 0; h < HH; h++) {
        const float* qh = qb + h * QKS;
        const float* kh = kb + h * QKS;
        float4 q4 = __ldg((const float4*)qh + lane);
        float4 k4 = __ldg((const float4*)kh + lane);
        float p = q4.x * k4.x + q4.y * k4.y + q4.z * k4.z + q4.w * k4.w;
        if (lane == 0) p = fmaf(-__ldg(qh + 128), __ldg(kh + 128), p); // Minkowski time term
        p = fmaf(CHALF * efl, __ldg(We + h * EDD + lane), p);          // edge-feature term
        part[h] = p;
    }
#pragma unroll
    for (int off = 16; off > 0; off >>= 1) {
#pragma unroll
        for (int h = 0; h < HH; h++)
            part[h] += __shfl_xor_sync(0xffffffffu, part[h], off);
    }
    if (lane < HH) {
        float logit = (2.f + 2.f * part[lane]) * SCALE_INV;
        g_logits[(size_t)w * HH + lane] = logit;
        atomicMaxF(&g_m[(size_t)d * HH + lane], logit);
    }
}

// thread per (edge, head): exp + segment sum of denominator
__global__ void k_edge2(const int* __restrict__ ei) {
    int idx = blockIdx.x * blockDim.x + threadIdx.x;
    if (idx >= EE * HH) return;
    int e = idx >> 2, h = idx & 3;
    int d = ei[EE + e];
    float ex = expf(g_logits[idx] - g_m[(size_t)d * HH + h]);
    g_logits[idx] = ex;
    atomicAdd(&g_den[(size_t)d * HH + h], ex);
}

// warp per edge: alpha * tan[src] scattered into agg[dst] via vector red
__global__ void k_edge3(const int* __restrict__ ei) {
    int w = (blockIdx.x * blockDim.x + threadIdx.x) >> 5;
    int lane = threadIdx.x & 31;
    if (w >= EE) return;
    int s = ei[w];
    int d = ei[EE + w];
    float a_l = 0.f;
    if (lane < HH) a_l = g_logits[(size_t)w * HH + lane] / g_den[(size_t)d * HH + lane];
    float alpha[HH];
#pragma unroll
    for (int h = 0; h < HH; h++) alpha[h] = __shfl_sync(0xffffffffu, a_l, h);

#pragma unroll
    for (int h = 0; h < HH; h++) {
        float4 t4 = __ldg((const float4*)(g_tan + ((size_t)s * HH + h) * DD) + lane);
        float* dp = g_agg + ((size_t)d * HH + h) * DD + lane * 4;
        asm volatile("red.global.add.v4.f32 [%0], {%1, %2, %3, %4};"
                     :: "l"(dp),
                        "f"(alpha[h] * t4.x), "f"(alpha[h] * t4.y),
                        "f"(alpha[h] * t4.z), "f"(alpha[h] * t4.w)
                     : "memory");
    }
}

// ---------------- output: mean over heads + expmap0 -------------------------
// warp per node
__global__ void k_out(float* __restrict__ out) {
    int w = (blockIdx.x * blockDim.x + threadIdx.x) >> 5;
    int lane = threadIdx.x & 31;
    if (w >= NN) return;
    float4 ms = make_float4(0.f, 0.f, 0.f, 0.f);
#pragma unroll
    for (int h = 0; h < HH; h++) {
        float4 v = ((const float4*)g_agg)[((size_t)w * HH + h) * 32 + lane];
        ms.x += v.x; ms.y += v.y; ms.z += v.z; ms.w += v.w;
    }
    ms.x *= 0.25f; ms.y *= 0.25f; ms.z *= 0.25f; ms.w *= 0.25f;
    float ss = ms.x * ms.x + ms.y * ms.y + ms.z * ms.z + ms.w * ms.w;
#pragma unroll
    for (int off = 16; off > 0; off >>= 1) ss += __shfl_xor_sync(0xffffffffu, ss, off);
    float nrm = sqrtf(ss);
    float f = sinhf(nrm) / fmaxf(nrm, EPSF);
    float* op = out + (size_t)w * KDIM;
    if (lane == 0) op[0] = coshf(nrm);
    float* sp = op + 1 + lane * 4;
    sp[0] = f * ms.x; sp[1] = f * ms.y; sp[2] = f * ms.z; sp[3] = f * ms.w;
}

// ---------------------------------------------------------------------------
extern "C" void kernel_launch(void* const* d_in, const int* in_sizes, int n_in,
                              void* d_out, int out_size) {
    const float* x  = (const float*)d_in[0];
    const int*   ei = (const int*)d_in[1];
    const float* ef = (const float*)d_in[2];
    const float* Wq = (const float*)d_in[3];
    const float* bq = (const float*)d_in[4];
    const float* Wk = (const float*)d_in[5];
    const float* bk = (const float*)d_in[6];
    const float* Wv = (const float*)d_in[7];
    const float* bv = (const float*)d_in[8];
    const float* We = (const float*)d_in[9];
    float* out = (float*)d_out;

    k_init<<<2048, 256>>>();
    k_gemm<<<dim3((NN + BM - 1) / BM, 12), 256>>>(x, Wq, bq, Wk, bk, Wv, bv);
    k_edge1<<<(EE * 32) / 256, 256>>>(ei, ef, We);
    k_edge2<<<(EE * HH + 255) / 256, 256>>>(ei);
    k_edge3<<<(EE * 32) / 256, 256>>>(ei);
    k_out<<<(NN * 32 + 255) / 256, 256>>>(out);
}